// round 12
// baseline (speedup 1.0000x reference)
#include <cuda_runtime.h>
#include <stdint.h>
#include <math.h>

#define L 512
#define DO 64      // D_ORIG
#define NH 8
#define DH 32
#define DE 256
#define SCALE 0.17677669529663687f  // 1/sqrt(32)

// Scratch (device globals — no allocations allowed)
__device__ float g_q[L*DE];
__device__ float g_k[L*DE];
__device__ float g_v[L*DE];
__device__ float g_p[L*512];            // [i][n*64+c], SCALE folded in
__device__ float g_sc[(size_t)NH*L*L];  // [n][i][j] base qk logits (SCALE folded)

#define CP_ASYNC16(sa, ga) asm volatile("cp.async.cg.shared.global [%0], [%1], 16;\n" :: "r"(sa), "l"(ga))
#define CP_COMMIT()        asm volatile("cp.async.commit_group;\n" ::: "memory")
#define CP_WAIT0()         asm volatile("cp.async.wait_group 0;\n" ::: "memory")

// ---------------------------------------------------------------------------
// Kernel 1: tiled GEMM  {q,k,v}[512x256] = x[512x64] @ W[64x256]
// ---------------------------------------------------------------------------
__global__ void proj_kernel(const float* __restrict__ x, const float* __restrict__ Wq,
                            const float* __restrict__ Wk, const float* __restrict__ Wv) {
    const float* W = (blockIdx.z == 0) ? Wq : (blockIdx.z == 1) ? Wk : Wv;
    float* outp    = (blockIdx.z == 0) ? g_q : (blockIdx.z == 1) ? g_k : g_v;
    int c0 = blockIdx.x * 64, i0 = blockIdx.y * 64;
    int t = threadIdx.x;
    __shared__ __align__(16) float xs[64][68];
    __shared__ __align__(16) float ws[64][68];
    for (int l = t; l < 1024; l += 256) {
        int r = l >> 4, c4 = (l & 15) * 4;
        *(float4*)&xs[r][c4] = *(const float4*)&x[(i0 + r)*DO + c4];
        *(float4*)&ws[r][c4] = *(const float4*)&W[r*DE + c0 + c4];
    }
    __syncthreads();
    int ty = t >> 4, tx = t & 15;
    float acc[4][4] = {};
    #pragma unroll
    for (int k = 0; k < 64; k++) {
        float4 b = *(const float4*)&ws[k][tx*4];
        float a0 = xs[ty*4+0][k], a1 = xs[ty*4+1][k], a2 = xs[ty*4+2][k], a3 = xs[ty*4+3][k];
        acc[0][0] = fmaf(a0, b.x, acc[0][0]); acc[0][1] = fmaf(a0, b.y, acc[0][1]);
        acc[0][2] = fmaf(a0, b.z, acc[0][2]); acc[0][3] = fmaf(a0, b.w, acc[0][3]);
        acc[1][0] = fmaf(a1, b.x, acc[1][0]); acc[1][1] = fmaf(a1, b.y, acc[1][1]);
        acc[1][2] = fmaf(a1, b.z, acc[1][2]); acc[1][3] = fmaf(a1, b.w, acc[1][3]);
        acc[2][0] = fmaf(a2, b.x, acc[2][0]); acc[2][1] = fmaf(a2, b.y, acc[2][1]);
        acc[2][2] = fmaf(a2, b.z, acc[2][2]); acc[2][3] = fmaf(a2, b.w, acc[2][3]);
        acc[3][0] = fmaf(a3, b.x, acc[3][0]); acc[3][1] = fmaf(a3, b.y, acc[3][1]);
        acc[3][2] = fmaf(a3, b.z, acc[3][2]); acc[3][3] = fmaf(a3, b.w, acc[3][3]);
    }
    #pragma unroll
    for (int m = 0; m < 4; m++)
        *(float4*)&outp[(i0 + ty*4 + m)*DE + c0 + tx*4] = *(float4*)&acc[m][0];
}

// ---------------------------------------------------------------------------
// Kernel 1b: p[i][n*64+c] = SCALE * sum_d q[i][n*32+d] * We[c][n*32+d]
// ---------------------------------------------------------------------------
__global__ void p_kernel(const float* __restrict__ We) {
    int i0 = blockIdx.x * 64, n = blockIdx.y;
    int t = threadIdx.x;
    __shared__ __align__(16) float qs[64][36];
    __shared__ __align__(16) float wes[32][68];
    for (int l = t; l < 512; l += 256) {
        int r = l >> 3, d4 = (l & 7) * 4;
        *(float4*)&qs[r][d4] = *(const float4*)&g_q[(i0 + r)*DE + n*DH + d4];
    }
    for (int l = t; l < 512; l += 256) {
        int c = l >> 3, d4 = (l & 7) * 4;
        float4 v4 = *(const float4*)&We[c*DE + n*DH + d4];
        wes[d4 + 0][c] = v4.x; wes[d4 + 1][c] = v4.y;
        wes[d4 + 2][c] = v4.z; wes[d4 + 3][c] = v4.w;
    }
    __syncthreads();
    int ty = t >> 4, tx = t & 15;
    float acc[4][4] = {};
    #pragma unroll
    for (int d = 0; d < 32; d++) {
        float4 b = *(const float4*)&wes[d][tx*4];
        float a0 = qs[ty*4+0][d], a1 = qs[ty*4+1][d], a2 = qs[ty*4+2][d], a3 = qs[ty*4+3][d];
        acc[0][0] = fmaf(a0, b.x, acc[0][0]); acc[0][1] = fmaf(a0, b.y, acc[0][1]);
        acc[0][2] = fmaf(a0, b.z, acc[0][2]); acc[0][3] = fmaf(a0, b.w, acc[0][3]);
        acc[1][0] = fmaf(a1, b.x, acc[1][0]); acc[1][1] = fmaf(a1, b.y, acc[1][1]);
        acc[1][2] = fmaf(a1, b.z, acc[1][2]); acc[1][3] = fmaf(a1, b.w, acc[1][3]);
        acc[2][0] = fmaf(a2, b.x, acc[2][0]); acc[2][1] = fmaf(a2, b.y, acc[2][1]);
        acc[2][2] = fmaf(a2, b.z, acc[2][2]); acc[2][3] = fmaf(a2, b.w, acc[2][3]);
        acc[3][0] = fmaf(a3, b.x, acc[3][0]); acc[3][1] = fmaf(a3, b.y, acc[3][1]);
        acc[3][2] = fmaf(a3, b.z, acc[3][2]); acc[3][3] = fmaf(a3, b.w, acc[3][3]);
    }
    #pragma unroll
    for (int m = 0; m < 4; m++) {
        #pragma unroll
        for (int j = 0; j < 4; j++) acc[m][j] *= SCALE;
        *(float4*)&g_p[(i0 + ty*4 + m)*512 + n*64 + tx*4] = *(float4*)&acc[m][0];
    }
}

// ---------------------------------------------------------------------------
// Kernel 2: base[n][i][j] = scale * q[i,nslice] . k[j,nslice]
// ---------------------------------------------------------------------------
__global__ void qk_kernel() {
    int n = blockIdx.z, i0 = blockIdx.y * 32, j0 = blockIdx.x * 32;
    int t = threadIdx.x;
    __shared__ float Qs[32][33], Ks[32][33];
    for (int l = t; l < 1024; l += 256) {
        int r = l >> 5, d = l & 31;
        Qs[r][d] = g_q[(i0 + r)*DE + n*DH + d];
        Ks[r][d] = g_k[(j0 + r)*DE + n*DH + d];
    }
    __syncthreads();
    int tx = t & 31, ty = t >> 5;
    float acc[4] = {0.f, 0.f, 0.f, 0.f};
    #pragma unroll
    for (int d = 0; d < 32; d++) {
        float kv = Ks[tx][d];
        #pragma unroll
        for (int m = 0; m < 4; m++) acc[m] = fmaf(Qs[ty*4 + m][d], kv, acc[m]);
    }
    #pragma unroll
    for (int m = 0; m < 4; m++)
        g_sc[((size_t)n*L + (i0 + ty*4 + m))*L + j0 + tx] = acc[m] * SCALE;
}

// ---------------------------------------------------------------------------
// Kernel 3 (hot): R7 warp-autonomous fused attention + two stall cuts:
// pes_t transposed pe reads (no dynamic-indexed LDS) and g_sc prefetch.
// 1 CTA per query i, warp owns 8 j-rows of each 64-row tile, no CTA barrier
// in the loop, cp.async double-buffered e-tiles, fused output projection.
// ---------------------------------------------------------------------------
__global__ void __launch_bounds__(256, 5)
attn_kernel(const float* __restrict__ e, const float* __restrict__ We,
            const float* __restrict__ Wo, const float* __restrict__ bo,
            float* __restrict__ out) {
    int i = blockIdx.x, t = threadIdx.x;
    int w = t >> 5, lane = t & 31;
    int cq = lane >> 3, jg = lane & 7;    // phase-A: quarter cq, row jg
    int jl = w*8 + jg;                    // local j row owned in phase A
    int vh = lane >> 3;                   // head of v-column 4*lane

    __shared__ __align__(16) float espool[2*4352];   // [2][64][68]
    __shared__ __align__(16) float ps[512];
    __shared__ __align__(16) float pes[64*8];        // [j_local][head]
    __shared__ __align__(16) float pes_t[8*64];      // [head][j_local]
    __shared__ float svals[NH];

    const float* ebase = e + (size_t)i*L*DO;
    unsigned es_sa = (unsigned)__cvta_generic_to_shared(espool);

    // prologue: warp w prefetches ITS 8 rows of tile 0 into buffer 0
    #pragma unroll
    for (int k2 = 0; k2 < 4; k2++) {
        int f = k2*32 + lane;
        int row = w*8 + (f >> 4), c4 = (f & 15) * 4;
        CP_ASYNC16(es_sa + (unsigned)(row*68 + c4)*4, ebase + (size_t)row*64 + c4);
    }
    CP_COMMIT();

    ps[t]       = g_p[i*512 + t];
    ps[t + 256] = g_p[i*512 + t + 256];
    // prefetch tile-0 base logits into registers
    float cur0 = g_sc[((size_t)(2*cq)*L + i)*L + jl];
    float cur1 = g_sc[((size_t)(2*cq + 1)*L + i)*L + jl];
    __syncthreads();    // ps visible to all warps

    float sacc0 = 0.f, sacc1 = 0.f;
    float wacc[16];
    #pragma unroll
    for (int n = 0; n < 16; n++) wacc[n] = 0.f;
    float4 va = make_float4(0.f,0.f,0.f,0.f), vb = make_float4(0.f,0.f,0.f,0.f);

    const float4* psf = (const float4*)ps;

    for (int tile = 0; tile < 8; tile++) {
        int b = tile & 1, j0 = tile * 64;
        CP_WAIT0();
        __syncwarp();     // prev phase-C reads of pes done before overwrite

        if (tile < 7) {   // prefetch own rows of next tile into other buffer
            #pragma unroll
            for (int k2 = 0; k2 < 4; k2++) {
                int f = k2*32 + lane;
                int row = w*8 + (f >> 4), c4 = (f & 15) * 4;
                CP_ASYNC16(es_sa + (unsigned)((b^1)*4352 + row*68 + c4)*4,
                           ebase + (size_t)(j0 + 64)*64 + (size_t)row*64 + c4);
            }
            CP_COMMIT();
        }
        // prefetch next tile's base logits (hide LDG latency under compute)
        float nxt0 = 0.f, nxt1 = 0.f;
        if (tile < 7) {
            nxt0 = g_sc[((size_t)(2*cq)*L + i)*L + (j0 + 64 + jl)];
            nxt1 = g_sc[((size_t)(2*cq + 1)*L + i)*L + (j0 + 64 + jl)];
        }

        // ---- Phase A: scores for row jl, ALL heads. Quarter cq of 64 cols.
        {
            const float4* er = (const float4*)&espool[b*4352 + jl*68];
            float4 ev0 = er[cq*4 + 0], ev1 = er[cq*4 + 1];
            float4 ev2 = er[cq*4 + 2], ev3 = er[cq*4 + 3];
            float accs[8];
            #pragma unroll
            for (int n = 0; n < 8; n++) {
                const float4* pq = psf + n*16 + cq*4;
                float4 p0 = pq[0], p1 = pq[1], p2 = pq[2], p3 = pq[3];
                float a = 0.f;
                a = fmaf(ev0.x, p0.x, a); a = fmaf(ev0.y, p0.y, a);
                a = fmaf(ev0.z, p0.z, a); a = fmaf(ev0.w, p0.w, a);
                a = fmaf(ev1.x, p1.x, a); a = fmaf(ev1.y, p1.y, a);
                a = fmaf(ev1.z, p1.z, a); a = fmaf(ev1.w, p1.w, a);
                a = fmaf(ev2.x, p2.x, a); a = fmaf(ev2.y, p2.y, a);
                a = fmaf(ev2.z, p2.z, a); a = fmaf(ev2.w, p2.w, a);
                a = fmaf(ev3.x, p3.x, a); a = fmaf(ev3.y, p3.y, a);
                a = fmaf(ev3.z, p3.z, a); a = fmaf(ev3.w, p3.w, a);
                accs[n] = a;
            }
            #pragma unroll
            for (int off = 8; off <= 16; off <<= 1)
                #pragma unroll
                for (int n = 0; n < 8; n++)
                    accs[n] += __shfl_xor_sync(0xffffffffu, accs[n], off);
            float pe0 = __expf(accs[2*cq] + cur0);
            float pe1 = __expf(accs[2*cq + 1] + cur1);
            sacc0 += pe0; sacc1 += pe1;
            *(float2*)&pes[jl*8 + 2*cq] = make_float2(pe0, pe1);
            pes_t[(2*cq)*64 + jl]     = pe0;
            pes_t[(2*cq + 1)*64 + jl] = pe1;
        }
        cur0 = nxt0; cur1 = nxt1;
        __syncwarp();     // pes/pes_t rows of this warp visible warp-wide

        // ---- Phase C: edge-weights + attn@v over OWN 8 rows
        float2 pa2 = make_float2(0.f,0.f), pb2 = make_float2(0.f,0.f);
        #pragma unroll
        for (int q = 0; q < 8; q++) {
            int jj = w*8 + q;
            const float* prow = &pes[jj*8];
            float2 p01 = *(const float2*)&prow[0];
            float2 p23 = *(const float2*)&prow[2];
            float2 p45 = *(const float2*)&prow[4];
            float2 p67 = *(const float2*)&prow[6];
            float2 ee = *(const float2*)&espool[b*4352 + jj*68 + 2*lane];
            wacc[0]  = fmaf(p01.x, ee.x, wacc[0]);  wacc[1]  = fmaf(p01.x, ee.y, wacc[1]);
            wacc[2]  = fmaf(p01.y, ee.x, wacc[2]);  wacc[3]  = fmaf(p01.y, ee.y, wacc[3]);
            wacc[4]  = fmaf(p23.x, ee.x, wacc[4]);  wacc[5]  = fmaf(p23.x, ee.y, wacc[5]);
            wacc[6]  = fmaf(p23.y, ee.x, wacc[6]);  wacc[7]  = fmaf(p23.y, ee.y, wacc[7]);
            wacc[8]  = fmaf(p45.x, ee.x, wacc[8]);  wacc[9]  = fmaf(p45.x, ee.y, wacc[9]);
            wacc[10] = fmaf(p45.y, ee.x, wacc[10]); wacc[11] = fmaf(p45.y, ee.y, wacc[11]);
            wacc[12] = fmaf(p67.x, ee.x, wacc[12]); wacc[13] = fmaf(p67.x, ee.y, wacc[13]);
            wacc[14] = fmaf(p67.y, ee.x, wacc[14]); wacc[15] = fmaf(p67.y, ee.y, wacc[15]);
            // attn@v: pe scalars via transposed layout (broadcast LDS.64 per 2q)
            if ((q & 1) == 0) {
                pa2 = *(const float2*)&pes_t[vh*64 + jj];
                pb2 = *(const float2*)&pes_t[(vh + 4)*64 + jj];
            }
            float pva = (q & 1) ? pa2.y : pa2.x;
            float pvb = (q & 1) ? pb2.y : pb2.x;
            const float4* vv = (const float4*)&g_v[(size_t)(j0 + jj)*DE];
            float4 v0 = vv[lane];
            float4 v1 = vv[lane + 32];
            va.x = fmaf(pva, v0.x, va.x); va.y = fmaf(pva, v0.y, va.y);
            va.z = fmaf(pva, v0.z, va.z); va.w = fmaf(pva, v0.w, va.w);
            vb.x = fmaf(pvb, v1.x, vb.x); vb.y = fmaf(pvb, v1.y, vb.y);
            vb.z = fmaf(pvb, v1.z, vb.z); vb.w = fmaf(pvb, v1.w, vb.w);
        }
    }

    // ---------------- Tail: cross-warp reductions + projections
    __syncthreads();
    float* wpart = espool;            // [8 warps][8 heads][64 c] = 4096 floats
    float* vred  = espool + 4352;     // [8 warps][256]           = 2048
    float* stmp  = espool + 6400;     // [8 heads][64]            = 512
    float* att   = espool + 6912;     // [256]
    float* opart = espool + 7168;     // [4][64]                  = 256
    float* wfin  = espool + 7424;     // [8 heads][64]            = 512

    #pragma unroll
    for (int n = 0; n < 8; n++)
        *(float2*)&wpart[(w*8 + n)*64 + 2*lane] = make_float2(wacc[2*n], wacc[2*n + 1]);
    *(float4*)&vred[w*256 + 4*lane]       = va;
    *(float4*)&vred[w*256 + 128 + 4*lane] = vb;
    stmp[(2*cq)*64 + jl]     = sacc0;
    stmp[(2*cq + 1)*64 + jl] = sacc1;
    __syncthreads();

    {   // softmax denominators: warp n reduces head n
        float sv = stmp[w*64 + lane] + stmp[w*64 + lane + 32];
        #pragma unroll
        for (int off = 16; off; off >>= 1) sv += __shfl_xor_sync(0xffffffffu, sv, off);
        if (lane == 0) svals[w] = sv;
    }
    {   // wfin[n][c] = sum over warps; thread t covers (t>>6, t&63) and (+4, t&63)
        int n0 = t >> 6, c0 = t & 63;
        float f0 = 0.f, f1 = 0.f;
        #pragma unroll
        for (int sw = 0; sw < 8; sw++) {
            f0 += wpart[(sw*8 + n0)*64 + c0];
            f1 += wpart[(sw*8 + n0 + 4)*64 + c0];
        }
        wfin[n0*64 + c0] = f0; wfin[(n0 + 4)*64 + c0] = f1;
    }
    __syncthreads();

    {   // att[t] = (attn@v + edge-weight @ We)/s
        int n = t >> 5;
        const float* wn = &wfin[n*64];
        float e0 = 0.f, e1 = 0.f;
        #pragma unroll
        for (int c = 0; c < 64; c += 2) {
            e0 = fmaf(wn[c],     We[c*DE + t],       e0);
            e1 = fmaf(wn[c + 1], We[(c + 1)*DE + t], e1);
        }
        float vsum = 0.f;
        #pragma unroll
        for (int sw = 0; sw < 8; sw++) vsum += vred[sw*256 + t];
        att[t] = (vsum + e0 + e1) / svals[n];
    }
    __syncthreads();

    {   // out = att@Wo + bo : 64 outputs x 4-way k-split
        int o = t & 63, kq = t >> 6;
        float a = 0.f;
        #pragma unroll
        for (int kk = 0; kk < 64; kk++) {
            int k = kq*64 + kk;
            a = fmaf(att[k], Wo[k*DO + o], a);
        }
        opart[kq*64 + o] = a;
    }
    __syncthreads();
    if (t < DO)
        out[i*DO + t] = bo[t] + opart[t] + opart[64 + t] + opart[128 + t] + opart[192 + t];
}

// ---------------------------------------------------------------------------
extern "C" void kernel_launch(void* const* d_in, const int* in_sizes, int n_in,
                              void* d_out, int out_size) {
    const float* x  = (const float*)d_in[0];
    const float* e  = (const float*)d_in[1];
    const float* Wq = (const float*)d_in[2];
    const float* Wk = (const float*)d_in[3];
    const float* Wv = (const float*)d_in[4];
    const float* We = (const float*)d_in[5];
    const float* Wo = (const float*)d_in[6];
    const float* bo = (const float*)d_in[7];
    float* out = (float*)d_out;

    proj_kernel<<<dim3(4, 8, 3), 256>>>(x, Wq, Wk, Wv);
    p_kernel<<<dim3(8, 8), 256>>>(We);
    qk_kernel<<<dim3(16, 16, 8), 256>>>();
    attn_kernel<<<512, 256>>>(e, We, Wo, bo, out);
}

// round 13
// speedup vs baseline: 1.3700x; 1.3700x over previous
#include <cuda_runtime.h>
#include <stdint.h>
#include <math.h>

#define L 512
#define DO 64      // D_ORIG
#define NH 8
#define DH 32
#define DE 256
#define SCALE 0.17677669529663687f  // 1/sqrt(32)

// Scratch (device globals — no allocations allowed)
__device__ float g_q[L*DE];
__device__ float g_k[L*DE];
__device__ float g_v[L*DE];
__device__ float g_p[L*512];            // [i][n*64+c], SCALE folded in
__device__ float g_sc[(size_t)NH*L*L];  // [n][i][j] base qk logits (SCALE folded)

#define CP_ASYNC16(sa, ga) asm volatile("cp.async.cg.shared.global [%0], [%1], 16;\n" :: "r"(sa), "l"(ga))
#define CP_COMMIT()        asm volatile("cp.async.commit_group;\n" ::: "memory")
#define CP_WAIT0()         asm volatile("cp.async.wait_group 0;\n" ::: "memory")

// ---------------------------------------------------------------------------
// Kernel 1: tiled GEMM  {q,k,v}[512x256] = x[512x64] @ W[64x256]
// ---------------------------------------------------------------------------
__global__ void proj_kernel(const float* __restrict__ x, const float* __restrict__ Wq,
                            const float* __restrict__ Wk, const float* __restrict__ Wv) {
    const float* W = (blockIdx.z == 0) ? Wq : (blockIdx.z == 1) ? Wk : Wv;
    float* outp    = (blockIdx.z == 0) ? g_q : (blockIdx.z == 1) ? g_k : g_v;
    int c0 = blockIdx.x * 64, i0 = blockIdx.y * 64;
    int t = threadIdx.x;
    __shared__ __align__(16) float xs[64][68];
    __shared__ __align__(16) float ws[64][68];
    for (int l = t; l < 1024; l += 256) {
        int r = l >> 4, c4 = (l & 15) * 4;
        *(float4*)&xs[r][c4] = *(const float4*)&x[(i0 + r)*DO + c4];
        *(float4*)&ws[r][c4] = *(const float4*)&W[r*DE + c0 + c4];
    }
    __syncthreads();
    int ty = t >> 4, tx = t & 15;
    float acc[4][4] = {};
    #pragma unroll
    for (int k = 0; k < 64; k++) {
        float4 b = *(const float4*)&ws[k][tx*4];
        float a0 = xs[ty*4+0][k], a1 = xs[ty*4+1][k], a2 = xs[ty*4+2][k], a3 = xs[ty*4+3][k];
        acc[0][0] = fmaf(a0, b.x, acc[0][0]); acc[0][1] = fmaf(a0, b.y, acc[0][1]);
        acc[0][2] = fmaf(a0, b.z, acc[0][2]); acc[0][3] = fmaf(a0, b.w, acc[0][3]);
        acc[1][0] = fmaf(a1, b.x, acc[1][0]); acc[1][1] = fmaf(a1, b.y, acc[1][1]);
        acc[1][2] = fmaf(a1, b.z, acc[1][2]); acc[1][3] = fmaf(a1, b.w, acc[1][3]);
        acc[2][0] = fmaf(a2, b.x, acc[2][0]); acc[2][1] = fmaf(a2, b.y, acc[2][1]);
        acc[2][2] = fmaf(a2, b.z, acc[2][2]); acc[2][3] = fmaf(a2, b.w, acc[2][3]);
        acc[3][0] = fmaf(a3, b.x, acc[3][0]); acc[3][1] = fmaf(a3, b.y, acc[3][1]);
        acc[3][2] = fmaf(a3, b.z, acc[3][2]); acc[3][3] = fmaf(a3, b.w, acc[3][3]);
    }
    #pragma unroll
    for (int m = 0; m < 4; m++)
        *(float4*)&outp[(i0 + ty*4 + m)*DE + c0 + tx*4] = *(float4*)&acc[m][0];
}

// ---------------------------------------------------------------------------
// Kernel 1b: p[i][n*64+c] = SCALE * sum_d q[i][n*32+d] * We[c][n*32+d]
// ---------------------------------------------------------------------------
__global__ void p_kernel(const float* __restrict__ We) {
    int i0 = blockIdx.x * 64, n = blockIdx.y;
    int t = threadIdx.x;
    __shared__ __align__(16) float qs[64][36];
    __shared__ __align__(16) float wes[32][68];
    for (int l = t; l < 512; l += 256) {
        int r = l >> 3, d4 = (l & 7) * 4;
        *(float4*)&qs[r][d4] = *(const float4*)&g_q[(i0 + r)*DE + n*DH + d4];
    }
    for (int l = t; l < 512; l += 256) {
        int c = l >> 3, d4 = (l & 7) * 4;
        float4 v4 = *(const float4*)&We[c*DE + n*DH + d4];
        wes[d4 + 0][c] = v4.x; wes[d4 + 1][c] = v4.y;
        wes[d4 + 2][c] = v4.z; wes[d4 + 3][c] = v4.w;
    }
    __syncthreads();
    int ty = t >> 4, tx = t & 15;
    float acc[4][4] = {};
    #pragma unroll
    for (int d = 0; d < 32; d++) {
        float4 b = *(const float4*)&wes[d][tx*4];
        float a0 = qs[ty*4+0][d], a1 = qs[ty*4+1][d], a2 = qs[ty*4+2][d], a3 = qs[ty*4+3][d];
        acc[0][0] = fmaf(a0, b.x, acc[0][0]); acc[0][1] = fmaf(a0, b.y, acc[0][1]);
        acc[0][2] = fmaf(a0, b.z, acc[0][2]); acc[0][3] = fmaf(a0, b.w, acc[0][3]);
        acc[1][0] = fmaf(a1, b.x, acc[1][0]); acc[1][1] = fmaf(a1, b.y, acc[1][1]);
        acc[1][2] = fmaf(a1, b.z, acc[1][2]); acc[1][3] = fmaf(a1, b.w, acc[1][3]);
        acc[2][0] = fmaf(a2, b.x, acc[2][0]); acc[2][1] = fmaf(a2, b.y, acc[2][1]);
        acc[2][2] = fmaf(a2, b.z, acc[2][2]); acc[2][3] = fmaf(a2, b.w, acc[2][3]);
        acc[3][0] = fmaf(a3, b.x, acc[3][0]); acc[3][1] = fmaf(a3, b.y, acc[3][1]);
        acc[3][2] = fmaf(a3, b.z, acc[3][2]); acc[3][3] = fmaf(a3, b.w, acc[3][3]);
    }
    #pragma unroll
    for (int m = 0; m < 4; m++) {
        #pragma unroll
        for (int j = 0; j < 4; j++) acc[m][j] *= SCALE;
        *(float4*)&g_p[(i0 + ty*4 + m)*512 + n*64 + tx*4] = *(float4*)&acc[m][0];
    }
}

// ---------------------------------------------------------------------------
// Kernel 2: base[n][i][j] = scale * q[i,nslice] . k[j,nslice]
// ---------------------------------------------------------------------------
__global__ void qk_kernel() {
    int n = blockIdx.z, i0 = blockIdx.y * 32, j0 = blockIdx.x * 32;
    int t = threadIdx.x;
    __shared__ float Qs[32][33], Ks[32][33];
    for (int l = t; l < 1024; l += 256) {
        int r = l >> 5, d = l & 31;
        Qs[r][d] = g_q[(i0 + r)*DE + n*DH + d];
        Ks[r][d] = g_k[(j0 + r)*DE + n*DH + d];
    }
    __syncthreads();
    int tx = t & 31, ty = t >> 5;
    float acc[4] = {0.f, 0.f, 0.f, 0.f};
    #pragma unroll
    for (int d = 0; d < 32; d++) {
        float kv = Ks[tx][d];
        #pragma unroll
        for (int m = 0; m < 4; m++) acc[m] = fmaf(Qs[ty*4 + m][d], kv, acc[m]);
    }
    #pragma unroll
    for (int m = 0; m < 4; m++)
        g_sc[((size_t)n*L + (i0 + ty*4 + m))*L + j0 + tx] = acc[m] * SCALE;
}

// ---------------------------------------------------------------------------
// Kernel 3 (hot): R7 warp-autonomous fused attention + cp.async staging of
// base logits (warp-local slice, no cross-warp dependency). 1 CTA per query,
// warp owns 8 j-rows per 64-row tile, no CTA barrier in the loop.
// ---------------------------------------------------------------------------
__global__ void __launch_bounds__(256, 4)
attn_kernel(const float* __restrict__ e, const float* __restrict__ We,
            const float* __restrict__ Wo, const float* __restrict__ bo,
            float* __restrict__ out) {
    int i = blockIdx.x, t = threadIdx.x;
    int w = t >> 5, lane = t & 31;
    int cq = lane >> 3, jg = lane & 7;    // phase-A mapping: quarter cq, row jg
    int jl = w*8 + jg;                    // local j row owned in phase A
    int vh = lane >> 3;                   // head of v-column 4*lane

    __shared__ __align__(16) float espool[2*4352];   // [2][64][68]
    __shared__ __align__(16) float ps[512];
    __shared__ __align__(16) float pes[64*8];        // [j_local][head]
    __shared__ __align__(16) float sb[2*512];        // [buf][warp][head][8j]
    __shared__ float svals[NH];

    const float* ebase = e + (size_t)i*L*DO;
    const float* scrow = g_sc + (size_t)i*L;         // + n*L*L + j
    unsigned es_sa = (unsigned)__cvta_generic_to_shared(espool);
    unsigned sb_sa = (unsigned)__cvta_generic_to_shared(sb);

    // prologue: warp w prefetches ITS rows of e-tile 0 + ITS logit slice
    #pragma unroll
    for (int k2 = 0; k2 < 4; k2++) {
        int f = k2*32 + lane;
        int row = w*8 + (f >> 4), c4 = (f & 15) * 4;
        CP_ASYNC16(es_sa + (unsigned)(row*68 + c4)*4, ebase + (size_t)row*64 + c4);
    }
    if (lane < 16) {   // logits for 8 heads x warp's 8 j's of tile 0
        int n = lane >> 1, half = lane & 1;
        CP_ASYNC16(sb_sa + (unsigned)(w*64 + n*8 + half*4)*4,
                   scrow + (size_t)n*L*L + w*8 + half*4);
    }
    CP_COMMIT();

    ps[t]       = g_p[i*512 + t];
    ps[t + 256] = g_p[i*512 + t + 256];
    __syncthreads();    // ps visible to all warps

    float sacc0 = 0.f, sacc1 = 0.f;
    float wacc[16];
    #pragma unroll
    for (int n = 0; n < 16; n++) wacc[n] = 0.f;
    float4 va = make_float4(0.f,0.f,0.f,0.f), vb = make_float4(0.f,0.f,0.f,0.f);

    const float4* psf = (const float4*)ps;

    for (int tile = 0; tile < 8; tile++) {
        int b = tile & 1, j0 = tile * 64;
        CP_WAIT0();
        __syncwarp();     // prev phase-C reads of pes done before overwrite

        if (tile < 7) {   // prefetch own rows of next tile into other buffer
            #pragma unroll
            for (int k2 = 0; k2 < 4; k2++) {
                int f = k2*32 + lane;
                int row = w*8 + (f >> 4), c4 = (f & 15) * 4;
                CP_ASYNC16(es_sa + (unsigned)((b^1)*4352 + row*68 + c4)*4,
                           ebase + (size_t)(j0 + 64)*64 + (size_t)row*64 + c4);
            }
            if (lane < 16) {   // next tile's logit slice
                int n = lane >> 1, half = lane & 1;
                CP_ASYNC16(sb_sa + (unsigned)((b^1)*512 + w*64 + n*8 + half*4)*4,
                           scrow + (size_t)n*L*L + j0 + 64 + w*8 + half*4);
            }
            CP_COMMIT();
        }

        // ---- Phase A: scores for row jl, ALL heads. Quarter cq of 64 cols.
        {
            const float4* er = (const float4*)&espool[b*4352 + jl*68];
            float4 ev0 = er[cq*4 + 0], ev1 = er[cq*4 + 1];
            float4 ev2 = er[cq*4 + 2], ev3 = er[cq*4 + 3];
            float accs[8];
            #pragma unroll
            for (int n = 0; n < 8; n++) {
                const float4* pq = psf + n*16 + cq*4;
                float4 p0 = pq[0], p1 = pq[1], p2 = pq[2], p3 = pq[3];
                float a = 0.f;
                a = fmaf(ev0.x, p0.x, a); a = fmaf(ev0.y, p0.y, a);
                a = fmaf(ev0.z, p0.z, a); a = fmaf(ev0.w, p0.w, a);
                a = fmaf(ev1.x, p1.x, a); a = fmaf(ev1.y, p1.y, a);
                a = fmaf(ev1.z, p1.z, a); a = fmaf(ev1.w, p1.w, a);
                a = fmaf(ev2.x, p2.x, a); a = fmaf(ev2.y, p2.y, a);
                a = fmaf(ev2.z, p2.z, a); a = fmaf(ev2.w, p2.w, a);
                a = fmaf(ev3.x, p3.x, a); a = fmaf(ev3.y, p3.y, a);
                a = fmaf(ev3.z, p3.z, a); a = fmaf(ev3.w, p3.w, a);
                accs[n] = a;
            }
            #pragma unroll
            for (int off = 8; off <= 16; off <<= 1)
                #pragma unroll
                for (int n = 0; n < 8; n++)
                    accs[n] += __shfl_xor_sync(0xffffffffu, accs[n], off);
            // base logits from cp.async-staged smem (written by THIS warp)
            float b0 = sb[b*512 + w*64 + (2*cq)*8 + jg];
            float b1 = sb[b*512 + w*64 + (2*cq + 1)*8 + jg];
            float pe0 = __expf(accs[2*cq] + b0);
            float pe1 = __expf(accs[2*cq + 1] + b1);
            sacc0 += pe0; sacc1 += pe1;
            *(float2*)&pes[jl*8 + 2*cq] = make_float2(pe0, pe1);
        }
        __syncwarp();     // pes rows of this warp visible warp-wide

        // ---- Phase C: edge-weights + attn@v over OWN 8 rows
        #pragma unroll
        for (int q = 0; q < 8; q++) {
            int jj = w*8 + q;
            const float* prow = &pes[jj*8];
            float2 p01 = *(const float2*)&prow[0];
            float2 p23 = *(const float2*)&prow[2];
            float2 p45 = *(const float2*)&prow[4];
            float2 p67 = *(const float2*)&prow[6];
            float2 ee = *(const float2*)&espool[b*4352 + jj*68 + 2*lane];
            wacc[0]  = fmaf(p01.x, ee.x, wacc[0]);  wacc[1]  = fmaf(p01.x, ee.y, wacc[1]);
            wacc[2]  = fmaf(p01.y, ee.x, wacc[2]);  wacc[3]  = fmaf(p01.y, ee.y, wacc[3]);
            wacc[4]  = fmaf(p23.x, ee.x, wacc[4]);  wacc[5]  = fmaf(p23.x, ee.y, wacc[5]);
            wacc[6]  = fmaf(p23.y, ee.x, wacc[6]);  wacc[7]  = fmaf(p23.y, ee.y, wacc[7]);
            wacc[8]  = fmaf(p45.x, ee.x, wacc[8]);  wacc[9]  = fmaf(p45.x, ee.y, wacc[9]);
            wacc[10] = fmaf(p45.y, ee.x, wacc[10]); wacc[11] = fmaf(p45.y, ee.y, wacc[11]);
            wacc[12] = fmaf(p67.x, ee.x, wacc[12]); wacc[13] = fmaf(p67.x, ee.y, wacc[13]);
            wacc[14] = fmaf(p67.y, ee.x, wacc[14]); wacc[15] = fmaf(p67.y, ee.y, wacc[15]);
            // attn@v: cols 4*lane (head vh) and 128+4*lane (head vh+4)
            const float4* vv = (const float4*)&g_v[(size_t)(j0 + jj)*DE];
            float4 v0 = vv[lane];
            float4 v1 = vv[lane + 32];
            float pva = prow[vh];
            float pvb = prow[4 + vh];
            va.x = fmaf(pva, v0.x, va.x); va.y = fmaf(pva, v0.y, va.y);
            va.z = fmaf(pva, v0.z, va.z); va.w = fmaf(pva, v0.w, va.w);
            vb.x = fmaf(pvb, v1.x, vb.x); vb.y = fmaf(pvb, v1.y, vb.y);
            vb.z = fmaf(pvb, v1.z, vb.z); vb.w = fmaf(pvb, v1.w, vb.w);
        }
    }

    // ---------------- Tail: cross-warp reductions + projections
    __syncthreads();
    float* wpart = espool;            // [8 warps][8 heads][64 c] = 4096 floats
    float* vred  = espool + 4352;     // [8 warps][256]           = 2048
    float* stmp  = espool + 6400;     // [8 heads][64]            = 512
    float* att   = espool + 6912;     // [256]
    float* opart = espool + 7168;     // [4][64]                  = 256
    float* wfin  = espool + 7424;     // [8 heads][64]            = 512

    #pragma unroll
    for (int n = 0; n < 8; n++)
        *(float2*)&wpart[(w*8 + n)*64 + 2*lane] = make_float2(wacc[2*n], wacc[2*n + 1]);
    *(float4*)&vred[w*256 + 4*lane]       = va;
    *(float4*)&vred[w*256 + 128 + 4*lane] = vb;
    stmp[(2*cq)*64 + jl]     = sacc0;
    stmp[(2*cq + 1)*64 + jl] = sacc1;
    __syncthreads();

    {   // softmax denominators: warp n reduces head n
        float sv = stmp[w*64 + lane] + stmp[w*64 + lane + 32];
        #pragma unroll
        for (int off = 16; off; off >>= 1) sv += __shfl_xor_sync(0xffffffffu, sv, off);
        if (lane == 0) svals[w] = sv;
    }
    {   // wfin[n][c] = sum over warps; thread t covers (t>>6, t&63) and (+4, t&63)
        int n0 = t >> 6, c0 = t & 63;
        float f0 = 0.f, f1 = 0.f;
        #pragma unroll
        for (int sw = 0; sw < 8; sw++) {
            f0 += wpart[(sw*8 + n0)*64 + c0];
            f1 += wpart[(sw*8 + n0 + 4)*64 + c0];
        }
        wfin[n0*64 + c0] = f0; wfin[(n0 + 4)*64 + c0] = f1;
    }
    __syncthreads();

    {   // att[t] = (attn@v + edge-weight @ We)/s
        int n = t >> 5;
        const float* wn = &wfin[n*64];
        float e0 = 0.f, e1 = 0.f;
        #pragma unroll
        for (int c = 0; c < 64; c += 2) {
            e0 = fmaf(wn[c],     We[c*DE + t],       e0);
            e1 = fmaf(wn[c + 1], We[(c + 1)*DE + t], e1);
        }
        float vsum = 0.f;
        #pragma unroll
        for (int sw = 0; sw < 8; sw++) vsum += vred[sw*256 + t];
        att[t] = (vsum + e0 + e1) / svals[n];
    }
    __syncthreads();

    {   // out = att@Wo + bo : 64 outputs x 4-way k-split
        int o = t & 63, kq = t >> 6;
        float a = 0.f;
        #pragma unroll
        for (int kk = 0; kk < 64; kk++) {
            int k = kq*64 + kk;
            a = fmaf(att[k], Wo[k*DO + o], a);
        }
        opart[kq*64 + o] = a;
    }
    __syncthreads();
    if (t < DO)
        out[i*DO + t] = bo[t] + opart[t] + opart[64 + t] + opart[128 + t] + opart[192 + t];
}

// ---------------------------------------------------------------------------
extern "C" void kernel_launch(void* const* d_in, const int* in_sizes, int n_in,
                              void* d_out, int out_size) {
    const float* x  = (const float*)d_in[0];
    const float* e  = (const float*)d_in[1];
    const float* Wq = (const float*)d_in[2];
    const float* Wk = (const float*)d_in[3];
    const float* Wv = (const float*)d_in[4];
    const float* We = (const float*)d_in[5];
    const float* Wo = (const float*)d_in[6];
    const float* bo = (const float*)d_in[7];
    float* out = (float*)d_out;

    proj_kernel<<<dim3(4, 8, 3), 256>>>(x, Wq, Wk, Wv);
    p_kernel<<<dim3(8, 8), 256>>>(We);
    qk_kernel<<<dim3(16, 16, 8), 256>>>();
    attn_kernel<<<512, 256>>>(e, We, Wo, bo, out);
}

// round 14
// speedup vs baseline: 1.3998x; 1.0217x over previous
#include <cuda_runtime.h>
#include <stdint.h>
#include <math.h>

#define L 512
#define DO 64      // D_ORIG
#define NH 8
#define DH 32
#define DE 256
#define SCALE 0.17677669529663687f  // 1/sqrt(32)

// Scratch (device globals — no allocations allowed)
__device__ float g_q[L*DE];
__device__ float g_k[L*DE];
__device__ float g_v[L*DE];
__device__ float g_p[L*512];            // [i][n*64+c], SCALE folded in
__device__ float g_sc[(size_t)NH*L*L];  // [n][i][j] base qk logits (SCALE folded)

#define CP_ASYNC16(sa, ga) asm volatile("cp.async.cg.shared.global [%0], [%1], 16;\n" :: "r"(sa), "l"(ga))
#define CP_COMMIT()        asm volatile("cp.async.commit_group;\n" ::: "memory")
#define CP_WAIT0()         asm volatile("cp.async.wait_group 0;\n" ::: "memory")

// ---------------------------------------------------------------------------
// Kernel 1: tiled GEMM  {q,k,v}[512x256] = x[512x64] @ W[64x256]
// ---------------------------------------------------------------------------
__global__ void proj_kernel(const float* __restrict__ x, const float* __restrict__ Wq,
                            const float* __restrict__ Wk, const float* __restrict__ Wv) {
    const float* W = (blockIdx.z == 0) ? Wq : (blockIdx.z == 1) ? Wk : Wv;
    float* outp    = (blockIdx.z == 0) ? g_q : (blockIdx.z == 1) ? g_k : g_v;
    int c0 = blockIdx.x * 64, i0 = blockIdx.y * 64;
    int t = threadIdx.x;
    __shared__ __align__(16) float xs[64][68];
    __shared__ __align__(16) float ws[64][68];
    for (int l = t; l < 1024; l += 256) {
        int r = l >> 4, c4 = (l & 15) * 4;
        *(float4*)&xs[r][c4] = *(const float4*)&x[(i0 + r)*DO + c4];
        *(float4*)&ws[r][c4] = *(const float4*)&W[r*DE + c0 + c4];
    }
    __syncthreads();
    int ty = t >> 4, tx = t & 15;
    float acc[4][4] = {};
    #pragma unroll
    for (int k = 0; k < 64; k++) {
        float4 b = *(const float4*)&ws[k][tx*4];
        float a0 = xs[ty*4+0][k], a1 = xs[ty*4+1][k], a2 = xs[ty*4+2][k], a3 = xs[ty*4+3][k];
        acc[0][0] = fmaf(a0, b.x, acc[0][0]); acc[0][1] = fmaf(a0, b.y, acc[0][1]);
        acc[0][2] = fmaf(a0, b.z, acc[0][2]); acc[0][3] = fmaf(a0, b.w, acc[0][3]);
        acc[1][0] = fmaf(a1, b.x, acc[1][0]); acc[1][1] = fmaf(a1, b.y, acc[1][1]);
        acc[1][2] = fmaf(a1, b.z, acc[1][2]); acc[1][3] = fmaf(a1, b.w, acc[1][3]);
        acc[2][0] = fmaf(a2, b.x, acc[2][0]); acc[2][1] = fmaf(a2, b.y, acc[2][1]);
        acc[2][2] = fmaf(a2, b.z, acc[2][2]); acc[2][3] = fmaf(a2, b.w, acc[2][3]);
        acc[3][0] = fmaf(a3, b.x, acc[3][0]); acc[3][1] = fmaf(a3, b.y, acc[3][1]);
        acc[3][2] = fmaf(a3, b.z, acc[3][2]); acc[3][3] = fmaf(a3, b.w, acc[3][3]);
    }
    #pragma unroll
    for (int m = 0; m < 4; m++)
        *(float4*)&outp[(i0 + ty*4 + m)*DE + c0 + tx*4] = *(float4*)&acc[m][0];
}

// ---------------------------------------------------------------------------
// Kernel 2 (merged): blockIdx.z 0..7 -> qk for head z; z==8 -> p GEMM.
// qk: base[n][i][j] = scale * q[i,nslice].k[j,nslice]  (32x32 tiles)
// p:  p[i][n*64+c]  = scale * sum_d q[i][n*32+d]*We[c][n*32+d]
// ---------------------------------------------------------------------------
__global__ void prep_kernel(const float* __restrict__ We) {
    int t = threadIdx.x;
    if (blockIdx.z < 8) {
        // ---- qk part: head n, 32x32 tile
        int n = blockIdx.z, i0 = blockIdx.y * 32, j0 = blockIdx.x * 32;
        __shared__ float Qs[32][33], Ks[32][33];
        for (int l = t; l < 1024; l += 256) {
            int r = l >> 5, d = l & 31;
            Qs[r][d] = g_q[(i0 + r)*DE + n*DH + d];
            Ks[r][d] = g_k[(j0 + r)*DE + n*DH + d];
        }
        __syncthreads();
        int tx = t & 31, ty = t >> 5;
        float acc[4] = {0.f, 0.f, 0.f, 0.f};
        #pragma unroll
        for (int d = 0; d < 32; d++) {
            float kv = Ks[tx][d];
            #pragma unroll
            for (int m = 0; m < 4; m++) acc[m] = fmaf(Qs[ty*4 + m][d], kv, acc[m]);
        }
        #pragma unroll
        for (int m = 0; m < 4; m++)
            g_sc[((size_t)n*L + (i0 + ty*4 + m))*L + j0 + tx] = acc[m] * SCALE;
    } else {
        // ---- p part: only (bx<8, by<8) tiles active: i-tile bx, head by
        if (blockIdx.x >= 8 || blockIdx.y >= 8) return;
        int i0 = blockIdx.x * 64, n = blockIdx.y;
        __shared__ __align__(16) float qs[64][36];
        __shared__ __align__(16) float wes[32][68];
        for (int l = t; l < 512; l += 256) {
            int r = l >> 3, d4 = (l & 7) * 4;
            *(float4*)&qs[r][d4] = *(const float4*)&g_q[(i0 + r)*DE + n*DH + d4];
        }
        for (int l = t; l < 512; l += 256) {
            int c = l >> 3, d4 = (l & 7) * 4;
            float4 v4 = *(const float4*)&We[c*DE + n*DH + d4];
            wes[d4 + 0][c] = v4.x; wes[d4 + 1][c] = v4.y;
            wes[d4 + 2][c] = v4.z; wes[d4 + 3][c] = v4.w;
        }
        __syncthreads();
        int ty = t >> 4, tx = t & 15;
        float acc[4][4] = {};
        #pragma unroll
        for (int d = 0; d < 32; d++) {
            float4 b = *(const float4*)&wes[d][tx*4];
            float a0 = qs[ty*4+0][d], a1 = qs[ty*4+1][d], a2 = qs[ty*4+2][d], a3 = qs[ty*4+3][d];
            acc[0][0] = fmaf(a0, b.x, acc[0][0]); acc[0][1] = fmaf(a0, b.y, acc[0][1]);
            acc[0][2] = fmaf(a0, b.z, acc[0][2]); acc[0][3] = fmaf(a0, b.w, acc[0][3]);
            acc[1][0] = fmaf(a1, b.x, acc[1][0]); acc[1][1] = fmaf(a1, b.y, acc[1][1]);
            acc[1][2] = fmaf(a1, b.z, acc[1][2]); acc[1][3] = fmaf(a1, b.w, acc[1][3]);
            acc[2][0] = fmaf(a2, b.x, acc[2][0]); acc[2][1] = fmaf(a2, b.y, acc[2][1]);
            acc[2][2] = fmaf(a2, b.z, acc[2][2]); acc[2][3] = fmaf(a2, b.w, acc[2][3]);
            acc[3][0] = fmaf(a3, b.x, acc[3][0]); acc[3][1] = fmaf(a3, b.y, acc[3][1]);
            acc[3][2] = fmaf(a3, b.z, acc[3][2]); acc[3][3] = fmaf(a3, b.w, acc[3][3]);
        }
        #pragma unroll
        for (int m = 0; m < 4; m++) {
            #pragma unroll
            for (int j = 0; j < 4; j++) acc[m][j] *= SCALE;
            *(float4*)&g_p[(i0 + ty*4 + m)*512 + n*64 + tx*4] = *(float4*)&acc[m][0];
        }
    }
}

// ---------------------------------------------------------------------------
// Kernel 3 (hot): R13 warp-autonomous fused attention (UNCHANGED — best 53.2us).
// cp.async staging of e-tiles AND base logits, warp owns 8 j-rows per tile,
// no CTA barrier in loop, fused output projection.
// ---------------------------------------------------------------------------
__global__ void __launch_bounds__(256, 4)
attn_kernel(const float* __restrict__ e, const float* __restrict__ We,
            const float* __restrict__ Wo, const float* __restrict__ bo,
            float* __restrict__ out) {
    int i = blockIdx.x, t = threadIdx.x;
    int w = t >> 5, lane = t & 31;
    int cq = lane >> 3, jg = lane & 7;    // phase-A mapping: quarter cq, row jg
    int jl = w*8 + jg;                    // local j row owned in phase A
    int vh = lane >> 3;                   // head of v-column 4*lane

    __shared__ __align__(16) float espool[2*4352];   // [2][64][68]
    __shared__ __align__(16) float ps[512];
    __shared__ __align__(16) float pes[64*8];        // [j_local][head]
    __shared__ __align__(16) float sb[2*512];        // [buf][warp][head][8j]
    __shared__ float svals[NH];

    const float* ebase = e + (size_t)i*L*DO;
    const float* scrow = g_sc + (size_t)i*L;         // + n*L*L + j
    unsigned es_sa = (unsigned)__cvta_generic_to_shared(espool);
    unsigned sb_sa = (unsigned)__cvta_generic_to_shared(sb);

    // prologue: warp w prefetches ITS rows of e-tile 0 + ITS logit slice
    #pragma unroll
    for (int k2 = 0; k2 < 4; k2++) {
        int f = k2*32 + lane;
        int row = w*8 + (f >> 4), c4 = (f & 15) * 4;
        CP_ASYNC16(es_sa + (unsigned)(row*68 + c4)*4, ebase + (size_t)row*64 + c4);
    }
    if (lane < 16) {   // logits for 8 heads x warp's 8 j's of tile 0
        int n = lane >> 1, half = lane & 1;
        CP_ASYNC16(sb_sa + (unsigned)(w*64 + n*8 + half*4)*4,
                   scrow + (size_t)n*L*L + w*8 + half*4);
    }
    CP_COMMIT();

    ps[t]       = g_p[i*512 + t];
    ps[t + 256] = g_p[i*512 + t + 256];
    __syncthreads();    // ps visible to all warps

    float sacc0 = 0.f, sacc1 = 0.f;
    float wacc[16];
    #pragma unroll
    for (int n = 0; n < 16; n++) wacc[n] = 0.f;
    float4 va = make_float4(0.f,0.f,0.f,0.f), vb = make_float4(0.f,0.f,0.f,0.f);

    const float4* psf = (const float4*)ps;

    for (int tile = 0; tile < 8; tile++) {
        int b = tile & 1, j0 = tile * 64;
        CP_WAIT0();
        __syncwarp();     // prev phase-C reads of pes done before overwrite

        if (tile < 7) {   // prefetch own rows of next tile into other buffer
            #pragma unroll
            for (int k2 = 0; k2 < 4; k2++) {
                int f = k2*32 + lane;
                int row = w*8 + (f >> 4), c4 = (f & 15) * 4;
                CP_ASYNC16(es_sa + (unsigned)((b^1)*4352 + row*68 + c4)*4,
                           ebase + (size_t)(j0 + 64)*64 + (size_t)row*64 + c4);
            }
            if (lane < 16) {   // next tile's logit slice
                int n = lane >> 1, half = lane & 1;
                CP_ASYNC16(sb_sa + (unsigned)((b^1)*512 + w*64 + n*8 + half*4)*4,
                           scrow + (size_t)n*L*L + j0 + 64 + w*8 + half*4);
            }
            CP_COMMIT();
        }

        // ---- Phase A: scores for row jl, ALL heads. Quarter cq of 64 cols.
        {
            const float4* er = (const float4*)&espool[b*4352 + jl*68];
            float4 ev0 = er[cq*4 + 0], ev1 = er[cq*4 + 1];
            float4 ev2 = er[cq*4 + 2], ev3 = er[cq*4 + 3];
            float accs[8];
            #pragma unroll
            for (int n = 0; n < 8; n++) {
                const float4* pq = psf + n*16 + cq*4;
                float4 p0 = pq[0], p1 = pq[1], p2 = pq[2], p3 = pq[3];
                float a = 0.f;
                a = fmaf(ev0.x, p0.x, a); a = fmaf(ev0.y, p0.y, a);
                a = fmaf(ev0.z, p0.z, a); a = fmaf(ev0.w, p0.w, a);
                a = fmaf(ev1.x, p1.x, a); a = fmaf(ev1.y, p1.y, a);
                a = fmaf(ev1.z, p1.z, a); a = fmaf(ev1.w, p1.w, a);
                a = fmaf(ev2.x, p2.x, a); a = fmaf(ev2.y, p2.y, a);
                a = fmaf(ev2.z, p2.z, a); a = fmaf(ev2.w, p2.w, a);
                a = fmaf(ev3.x, p3.x, a); a = fmaf(ev3.y, p3.y, a);
                a = fmaf(ev3.z, p3.z, a); a = fmaf(ev3.w, p3.w, a);
                accs[n] = a;
            }
            #pragma unroll
            for (int off = 8; off <= 16; off <<= 1)
                #pragma unroll
                for (int n = 0; n < 8; n++)
                    accs[n] += __shfl_xor_sync(0xffffffffu, accs[n], off);
            // base logits from cp.async-staged smem (written by THIS warp)
            float b0 = sb[b*512 + w*64 + (2*cq)*8 + jg];
            float b1 = sb[b*512 + w*64 + (2*cq + 1)*8 + jg];
            float pe0 = __expf(accs[2*cq] + b0);
            float pe1 = __expf(accs[2*cq + 1] + b1);
            sacc0 += pe0; sacc1 += pe1;
            *(float2*)&pes[jl*8 + 2*cq] = make_float2(pe0, pe1);
        }
        __syncwarp();     // pes rows of this warp visible warp-wide

        // ---- Phase C: edge-weights + attn@v over OWN 8 rows
        #pragma unroll
        for (int q = 0; q < 8; q++) {
            int jj = w*8 + q;
            const float* prow = &pes[jj*8];
            float2 p01 = *(const float2*)&prow[0];
            float2 p23 = *(const float2*)&prow[2];
            float2 p45 = *(const float2*)&prow[4];
            float2 p67 = *(const float2*)&prow[6];
            float2 ee = *(const float2*)&espool[b*4352 + jj*68 + 2*lane];
            wacc[0]  = fmaf(p01.x, ee.x, wacc[0]);  wacc[1]  = fmaf(p01.x, ee.y, wacc[1]);
            wacc[2]  = fmaf(p01.y, ee.x, wacc[2]);  wacc[3]  = fmaf(p01.y, ee.y, wacc[3]);
            wacc[4]  = fmaf(p23.x, ee.x, wacc[4]);  wacc[5]  = fmaf(p23.x, ee.y, wacc[5]);
            wacc[6]  = fmaf(p23.y, ee.x, wacc[6]);  wacc[7]  = fmaf(p23.y, ee.y, wacc[7]);
            wacc[8]  = fmaf(p45.x, ee.x, wacc[8]);  wacc[9]  = fmaf(p45.x, ee.y, wacc[9]);
            wacc[10] = fmaf(p45.y, ee.x, wacc[10]); wacc[11] = fmaf(p45.y, ee.y, wacc[11]);
            wacc[12] = fmaf(p67.x, ee.x, wacc[12]); wacc[13] = fmaf(p67.x, ee.y, wacc[13]);
            wacc[14] = fmaf(p67.y, ee.x, wacc[14]); wacc[15] = fmaf(p67.y, ee.y, wacc[15]);
            // attn@v: cols 4*lane (head vh) and 128+4*lane (head vh+4)
            const float4* vv = (const float4*)&g_v[(size_t)(j0 + jj)*DE];
            float4 v0 = vv[lane];
            float4 v1 = vv[lane + 32];
            float pva = prow[vh];
            float pvb = prow[4 + vh];
            va.x = fmaf(pva, v0.x, va.x); va.y = fmaf(pva, v0.y, va.y);
            va.z = fmaf(pva, v0.z, va.z); va.w = fmaf(pva, v0.w, va.w);
            vb.x = fmaf(pvb, v1.x, vb.x); vb.y = fmaf(pvb, v1.y, vb.y);
            vb.z = fmaf(pvb, v1.z, vb.z); vb.w = fmaf(pvb, v1.w, vb.w);
        }
    }

    // ---------------- Tail: cross-warp reductions + projections
    __syncthreads();
    float* wpart = espool;            // [8 warps][8 heads][64 c] = 4096 floats
    float* vred  = espool + 4352;     // [8 warps][256]           = 2048
    float* stmp  = espool + 6400;     // [8 heads][64]            = 512
    float* att   = espool + 6912;     // [256]
    float* opart = espool + 7168;     // [4][64]                  = 256
    float* wfin  = espool + 7424;     // [8 heads][64]            = 512

    #pragma unroll
    for (int n = 0; n < 8; n++)
        *(float2*)&wpart[(w*8 + n)*64 + 2*lane] = make_float2(wacc[2*n], wacc[2*n + 1]);
    *(float4*)&vred[w*256 + 4*lane]       = va;
    *(float4*)&vred[w*256 + 128 + 4*lane] = vb;
    stmp[(2*cq)*64 + jl]     = sacc0;
    stmp[(2*cq + 1)*64 + jl] = sacc1;
    __syncthreads();

    {   // softmax denominators: warp n reduces head n
        float sv = stmp[w*64 + lane] + stmp[w*64 + lane + 32];
        #pragma unroll
        for (int off = 16; off; off >>= 1) sv += __shfl_xor_sync(0xffffffffu, sv, off);
        if (lane == 0) svals[w] = sv;
    }
    {   // wfin[n][c] = sum over warps; thread t covers (t>>6, t&63) and (+4, t&63)
        int n0 = t >> 6, c0 = t & 63;
        float f0 = 0.f, f1 = 0.f;
        #pragma unroll
        for (int sw = 0; sw < 8; sw++) {
            f0 += wpart[(sw*8 + n0)*64 + c0];
            f1 += wpart[(sw*8 + n0 + 4)*64 + c0];
        }
        wfin[n0*64 + c0] = f0; wfin[(n0 + 4)*64 + c0] = f1;
    }
    __syncthreads();

    {   // att[t] = (attn@v + edge-weight @ We)/s
        int n = t >> 5;
        const float* wn = &wfin[n*64];
        float e0 = 0.f, e1 = 0.f;
        #pragma unroll
        for (int c = 0; c < 64; c += 2) {
            e0 = fmaf(wn[c],     We[c*DE + t],       e0);
            e1 = fmaf(wn[c + 1], We[(c + 1)*DE + t], e1);
        }
        float vsum = 0.f;
        #pragma unroll
        for (int sw = 0; sw < 8; sw++) vsum += vred[sw*256 + t];
        att[t] = (vsum + e0 + e1) / svals[n];
    }
    __syncthreads();

    {   // out = att@Wo + bo : 64 outputs x 4-way k-split
        int o = t & 63, kq = t >> 6;
        float a = 0.f;
        #pragma unroll
        for (int kk = 0; kk < 64; kk++) {
            int k = kq*64 + kk;
            a = fmaf(att[k], Wo[k*DO + o], a);
        }
        opart[kq*64 + o] = a;
    }
    __syncthreads();
    if (t < DO)
        out[i*DO + t] = bo[t] + opart[t] + opart[64 + t] + opart[128 + t] + opart[192 + t];
}

// ---------------------------------------------------------------------------
extern "C" void kernel_launch(void* const* d_in, const int* in_sizes, int n_in,
                              void* d_out, int out_size) {
    const float* x  = (const float*)d_in[0];
    const float* e  = (const float*)d_in[1];
    const float* Wq = (const float*)d_in[2];
    const float* Wk = (const float*)d_in[3];
    const float* Wv = (const float*)d_in[4];
    const float* We = (const float*)d_in[5];
    const float* Wo = (const float*)d_in[6];
    const float* bo = (const float*)d_in[7];
    float* out = (float*)d_out;

    proj_kernel<<<dim3(4, 8, 3), 256>>>(x, Wq, Wk, Wv);
    prep_kernel<<<dim3(16, 16, 9), 256>>>(We);
    attn_kernel<<<512, 256>>>(e, We, Wo, bo, out);
}